// round 3
// baseline (speedup 1.0000x reference)
#include <cuda_runtime.h>

#define N_NODES 20000
#define FMD 128
#define NH 8
#define OCD 128
#define N_EDGE 160000
#define ETOT 180000           /* E + self loops */
#define CIRCN 504
#define MIRN 19496            /* N - CIRC */
#define PQ 9825984            /* CIRC * MIRN */
#define HCOLS 1024            /* H * FM */

// ---------------- scratch (device globals; no runtime allocation) ----------
__device__ float    g_h[(size_t)N_NODES * HCOLS];   // 81.92 MB
__device__ float    g_s[N_NODES * NH];
__device__ float    g_d[N_NODES * NH];
__device__ unsigned g_menc[N_NODES * NH];
__device__ float    g_den[N_NODES * NH];
__device__ float    g_e[(size_t)ETOT * NH];         // 5.76 MB
__device__ int      g_deg[N_NODES];
__device__ int      g_off[N_NODES + 1];
__device__ int      g_cur[N_NODES];
__device__ int      g_srcS[ETOT];
__device__ int      g_eidS[ETOT];
__device__ int      g_srcC[ETOT];   // decoded src (with self loops)
__device__ int      g_dstC[ETOT];   // decoded dst (with self loops)
__device__ int      g_is64;         // edge_index dtype flag
__device__ float    g_x1[N_NODES * FMD];
__device__ float    g_x2[N_NODES * FMD];

// on-device buffer selection (NO host-side cudaGetSymbolAddress)
__device__ __forceinline__ const float* sel_in(int sel, const float* ext) {
    if (sel == 1) return g_x1;
    if (sel == 2) return g_x2;
    return ext;
}
__device__ __forceinline__ float* sel_out(int sel) {
    return (sel == 1) ? g_x1 : g_x2;
}

// ordered-uint encoding for float atomicMax
__device__ __forceinline__ unsigned fenc(float f) {
    unsigned u = __float_as_uint(f);
    return (u & 0x80000000u) ? ~u : (u | 0x80000000u);
}
__device__ __forceinline__ float fdec(unsigned u) {
    return (u & 0x80000000u) ? __uint_as_float(u & 0x7FFFFFFFu)
                             : __uint_as_float(~u);
}

// ---------------- edge-index dtype detect + decode -------------------------
__global__ void k_detect(const int* __restrict__ ei32) {
    // int64 non-negative values < 2^31  =>  every odd 32-bit word is 0.
    // int32 random values in [0,20000)  =>  P(16 odd words all zero) ~ 0.
    int allz = 1;
    #pragma unroll
    for (int i = 1; i < 32; i += 2)
        if (ei32[i] != 0) allz = 0;
    g_is64 = allz;
}

__global__ void k_decode(const void* __restrict__ ei) {
    int i = blockIdx.x * 256 + threadIdx.x;
    if (i >= ETOT) return;
    int src, dst;
    if (i < N_EDGE) {
        if (g_is64) {
            const long long* p = (const long long*)ei;
            src = (int)p[i];
            dst = (int)p[N_EDGE + i];
        } else {
            const int* p = (const int*)ei;
            src = p[i];
            dst = p[N_EDGE + i];
        }
    } else {
        src = dst = i - N_EDGE;
    }
    g_srcC[i] = src;
    g_dstC[i] = dst;
}

// ---------------- CSR build ------------------------------------------------
__global__ void k_zero_deg() {
    int i = blockIdx.x * 256 + threadIdx.x;
    if (i < N_NODES) g_deg[i] = 0;
}

__global__ void k_count() {
    int i = blockIdx.x * 256 + threadIdx.x;
    if (i >= ETOT) return;
    atomicAdd(&g_deg[g_dstC[i]], 1);
}

__global__ void __launch_bounds__(1024) k_scan() {
    __shared__ int sh[1024];
    __shared__ int carry;
    int t = threadIdx.x;
    if (t == 0) carry = 0;
    __syncthreads();
    for (int base = 0; base < N_NODES; base += 1024) {
        int i = base + t;
        int v = (i < N_NODES) ? g_deg[i] : 0;
        sh[t] = v;
        __syncthreads();
        for (int s = 1; s < 1024; s <<= 1) {
            int tmp = (t >= s) ? sh[t - s] : 0;
            __syncthreads();
            sh[t] += tmp;
            __syncthreads();
        }
        int excl = carry + sh[t] - v;
        if (i < N_NODES) { g_off[i] = excl; g_cur[i] = excl; }
        __syncthreads();
        if (t == 0) carry += sh[1023];
        __syncthreads();
    }
    if (t == 0) g_off[N_NODES] = carry;
}

__global__ void k_scatter() {
    int i = blockIdx.x * 256 + threadIdx.x;
    if (i >= ETOT) return;
    int pos = atomicAdd(&g_cur[g_dstC[i]], 1);
    g_srcS[pos] = g_srcC[i];
    g_eidS[pos] = i;
}

// ---------------- NN GEMM: g_h[M,1024] = A[M,128] * B[128,1024] ------------
__global__ void __launch_bounds__(256) gemm_nn(
    const float* __restrict__ Aext, int asel, const float* __restrict__ B,
    int M, int Nn, int K)
{
    const float* A = sel_in(asel, Aext);
    float* C = g_h;
    __shared__ float sA[64 * 68];
    __shared__ float sB[64 * 68];
    int m0 = blockIdx.x * 64, n0 = blockIdx.y * 64;
    int tid = threadIdx.x;
    int tx = tid & 15, ty = tid >> 4;
    float acc[4][4] = {};

    for (int kc = 0; kc < K; kc += 64) {
        #pragma unroll
        for (int p = 0; p < 4; p++) {
            int r  = p * 16 + (tid >> 4);
            int c4 = tid & 15;
            float4 va = make_float4(0.f, 0.f, 0.f, 0.f);
            if (m0 + r < M)
                va = *(const float4*)(A + (size_t)(m0 + r) * K + kc + c4 * 4);
            *(float4*)&sA[r * 68 + c4 * 4] = va;
            float4 vb = *(const float4*)(B + (size_t)(kc + r) * Nn + n0 + c4 * 4);
            *(float4*)&sB[r * 68 + c4 * 4] = vb;
        }
        __syncthreads();
        #pragma unroll
        for (int k = 0; k < 64; k += 4) {
            float4 a4[4], b4[4];
            #pragma unroll
            for (int i = 0; i < 4; i++)
                a4[i] = *(float4*)&sA[(ty * 4 + i) * 68 + k];
            #pragma unroll
            for (int kk = 0; kk < 4; kk++)
                b4[kk] = *(float4*)&sB[(k + kk) * 68 + tx * 4];
            #pragma unroll
            for (int i = 0; i < 4; i++) {
                const float* ap = (const float*)&a4[i];
                #pragma unroll
                for (int kk = 0; kk < 4; kk++) {
                    float av = ap[kk];
                    acc[i][0] += av * b4[kk].x;
                    acc[i][1] += av * b4[kk].y;
                    acc[i][2] += av * b4[kk].z;
                    acc[i][3] += av * b4[kk].w;
                }
            }
        }
        __syncthreads();
    }
    #pragma unroll
    for (int i = 0; i < 4; i++) {
        int m = m0 + ty * 4 + i;
        if (m < M) {
            float4 v = make_float4(acc[i][0], acc[i][1], acc[i][2], acc[i][3]);
            *(float4*)(C + (size_t)m * Nn + n0 + tx * 4) = v;
        }
    }
}

// ---------------- NT GEMM: C[M,Nn] = A[M,K] * B[Nn,K]^T --------------------
// DUAL: A is [g_x1 | g_x2] concatenated along K (each row-stride 128).
// CLS : add bias and route rows into circ/mir regions of d_out.
template <bool DUAL, bool CLS>
__global__ void __launch_bounds__(256) gemm_nt(
    const float* __restrict__ Aext,
    const float* __restrict__ B, const float* __restrict__ bias,
    float* __restrict__ C, int M, int Nn, int K)
{
    __shared__ float sA[64 * 68];
    __shared__ float sB[64 * 64];   // XOR chunk-swizzled
    int m0 = blockIdx.x * 64, n0 = blockIdx.y * 64;
    int tid = threadIdx.x;
    int tx = tid & 15, ty = tid >> 4;
    float acc[4][4] = {};

    for (int kc = 0; kc < K; kc += 64) {
        #pragma unroll
        for (int p = 0; p < 4; p++) {
            int r  = p * 16 + (tid >> 4);
            int c4 = tid & 15;
            float4 va = make_float4(0.f, 0.f, 0.f, 0.f);
            if (m0 + r < M) {
                const float* Ap;
                if (DUAL)
                    Ap = (kc < 128) ? (g_x1 + (size_t)(m0 + r) * 128 + kc)
                                    : (g_x2 + (size_t)(m0 + r) * 128 + (kc - 128));
                else
                    Ap = Aext + (size_t)(m0 + r) * K + kc;
                va = *(const float4*)(Ap + c4 * 4);
            }
            *(float4*)&sA[r * 68 + c4 * 4] = va;

            float4 vb = make_float4(0.f, 0.f, 0.f, 0.f);
            if (n0 + r < Nn)
                vb = *(const float4*)(B + (size_t)(n0 + r) * K + kc + c4 * 4);
            int cs = c4 ^ ((r >> 2) & 7);
            *(float4*)&sB[r * 64 + cs * 4] = vb;
        }
        __syncthreads();
        #pragma unroll
        for (int k = 0; k < 64; k += 4) {
            int kchunk = k >> 2;
            float4 a4[4], b4[4];
            #pragma unroll
            for (int i = 0; i < 4; i++)
                a4[i] = *(float4*)&sA[(ty * 4 + i) * 68 + k];
            #pragma unroll
            for (int j = 0; j < 4; j++) {
                int row = tx * 4 + j;
                int cs = kchunk ^ ((row >> 2) & 7);
                b4[j] = *(float4*)&sB[row * 64 + cs * 4];
            }
            #pragma unroll
            for (int i = 0; i < 4; i++) {
                const float* ap = (const float*)&a4[i];
                #pragma unroll
                for (int j = 0; j < 4; j++) {
                    const float* bp = (const float*)&b4[j];
                    acc[i][j] += ap[0] * bp[0] + ap[1] * bp[1]
                               + ap[2] * bp[2] + ap[3] * bp[3];
                }
            }
        }
        __syncthreads();
    }

    #pragma unroll
    for (int i = 0; i < 4; i++) {
        int m = m0 + ty * 4 + i;
        if (m >= M) continue;
        int ncol = n0 + tx * 4;
        if (CLS) {
            float4 v;
            v.x = acc[i][0] + bias[ncol + 0];
            v.y = acc[i][1] + bias[ncol + 1];
            v.z = acc[i][2] + bias[ncol + 2];
            v.w = acc[i][3] + bias[ncol + 3];
            float* base = (m < CIRCN)
                ? (C + PQ + (size_t)m * OCD)
                : (C + PQ + (size_t)CIRCN * OCD + (size_t)(m - CIRCN) * OCD);
            *(float4*)(base + ncol) = v;
        } else {
            if (ncol < Nn) {
                float4 v = make_float4(acc[i][0], acc[i][1], acc[i][2], acc[i][3]);
                *(float4*)(C + (size_t)m * Nn + ncol) = v;
            }
        }
    }
}

// ---------------- attention pieces -----------------------------------------
__global__ void __launch_bounds__(256) k_sd(
    const float* __restrict__ as, const float* __restrict__ ad)
{
    int n = blockIdx.x;
    int w = threadIdx.x >> 5, lane = threadIdx.x & 31;
    const float* hr = g_h + (size_t)n * HCOLS + w * FMD;
    const float* ar = as + w * FMD;
    const float* dr = ad + w * FMD;
    float s = 0.f, d = 0.f;
    #pragma unroll
    for (int j = 0; j < 4; j++) {
        int c = lane + j * 32;
        float hv = hr[c];
        s += hv * ar[c];
        d += hv * dr[c];
    }
    #pragma unroll
    for (int o = 16; o; o >>= 1) {
        s += __shfl_down_sync(0xffffffffu, s, o);
        d += __shfl_down_sync(0xffffffffu, d, o);
    }
    if (lane == 0) { g_s[n * NH + w] = s; g_d[n * NH + w] = d; }
}

__global__ void k_initmd() {
    int i = blockIdx.x * 256 + threadIdx.x;
    if (i < N_NODES * NH) { g_menc[i] = 0u; g_den[i] = 0.f; }
}

__global__ void k_emax() {
    int idx = blockIdx.x * 256 + threadIdx.x;
    if (idx >= ETOT * NH) return;
    int e = idx >> 3, hh = idx & 7;
    int src = g_srcC[e], dst = g_dstC[e];
    float v = g_s[src * NH + hh] + g_d[dst * NH + hh];
    v = (v > 0.f) ? v : 0.2f * v;
    g_e[idx] = v;
    atomicMax(&g_menc[dst * NH + hh], fenc(v));
}

__global__ void k_eexp() {
    int idx = blockIdx.x * 256 + threadIdx.x;
    if (idx >= ETOT * NH) return;
    int e = idx >> 3, hh = idx & 7;
    int dst = g_dstC[e];
    float m = fdec(g_menc[dst * NH + hh]);
    float ee = expf(g_e[idx] - m);
    g_e[idx] = ee;
    atomicAdd(&g_den[dst * NH + hh], ee);
}

// per-dst aggregation: xout[n,f] = relu(mean_h( sum_e alpha*h[src] ) + b[f])
__global__ void __launch_bounds__(128) k_agg(
    const float* __restrict__ bias, int osel)
{
    float* xout = sel_out(osel);
    int n = blockIdx.x;
    int f = threadIdx.x;
    float inv[NH];
    #pragma unroll
    for (int h = 0; h < NH; h++)
        inv[h] = 1.f / (g_den[n * NH + h] + 1e-16f);
    float acc[NH] = {};
    int e0 = g_off[n], e1 = g_off[n + 1];
    for (int j = e0; j < e1; j++) {
        int s   = g_srcS[j];
        int eid = g_eidS[j];
        const float* er = g_e + (size_t)eid * NH;
        const float* hr = g_h + (size_t)s * HCOLS + f;
        #pragma unroll
        for (int h = 0; h < NH; h++)
            acc[h] += er[h] * inv[h] * hr[h * FMD];
    }
    float sum = 0.f;
    #pragma unroll
    for (int h = 0; h < NH; h++) sum += acc[h];
    xout[(size_t)n * FMD + f] = fmaxf(sum * 0.125f + bias[f], 0.f);
}

// ---------------- launch ---------------------------------------------------
extern "C" void kernel_launch(void* const* d_in, const int* in_sizes, int n_in,
                              void* d_out, int out_size)
{
    const float* x   = (const float*)d_in[0];
    const void*  ei  = d_in[1];
    const float* W1  = (const float*)d_in[2];
    const float* as1 = (const float*)d_in[3];
    const float* ad1 = (const float*)d_in[4];
    const float* b1  = (const float*)d_in[5];
    const float* W2  = (const float*)d_in[6];
    const float* as2 = (const float*)d_in[7];
    const float* ad2 = (const float*)d_in[8];
    const float* b2  = (const float*)d_in[9];
    const float* Wc  = (const float*)d_in[10];
    const float* bc  = (const float*)d_in[11];
    float* out = (float*)d_out;

    // edge-index dtype detect + decode, then CSR build
    k_detect<<<1, 1>>>((const int*)ei);
    k_decode<<<(ETOT + 255) / 256, 256>>>(ei);
    k_zero_deg<<<(N_NODES + 255) / 256, 256>>>();
    k_count<<<(ETOT + 255) / 256, 256>>>();
    k_scan<<<1, 1024>>>();
    k_scatter<<<(ETOT + 255) / 256, 256>>>();

    dim3 gH((N_NODES + 63) / 64, HCOLS / 64);
    int gEH = (ETOT * NH + 255) / 256;
    int gMD = (N_NODES * NH + 255) / 256;

    // ---- layer 1 ----
    gemm_nn<<<gH, 256>>>(x, 0, W1, N_NODES, HCOLS, FMD);
    k_sd<<<N_NODES, 256>>>(as1, ad1);
    k_initmd<<<gMD, 256>>>();
    k_emax<<<gEH, 256>>>();
    k_eexp<<<gEH, 256>>>();
    k_agg<<<N_NODES, 128>>>(b1, 1);

    // ---- layer 2 ----
    gemm_nn<<<gH, 256>>>(nullptr, 1, W2, N_NODES, HCOLS, FMD);
    k_sd<<<N_NODES, 256>>>(as2, ad2);
    k_initmd<<<gMD, 256>>>();
    k_emax<<<gEH, 256>>>();
    k_eexp<<<gEH, 256>>>();
    k_agg<<<N_NODES, 128>>>(b2, 2);

    // ---- classifier: emb[n,o] = x1[n]·Wc[o,0] + x2[n]·Wc[o,1] + bc[o] ----
    dim3 gC((N_NODES + 63) / 64, OCD / 64);
    gemm_nt<true, true><<<gC, 256>>>(nullptr, Wc, bc, out,
                                     N_NODES, OCD, 2 * FMD);

    // ---- P = circ @ mir^T ----
    const float* circ = out + PQ;
    const float* mir  = out + PQ + (size_t)CIRCN * OCD;
    dim3 gP((CIRCN + 63) / 64, (MIRN + 63) / 64);
    gemm_nt<false, false><<<gP, 256>>>(circ, mir, nullptr, out,
                                       CIRCN, MIRN, FMD);
}